// round 14
// baseline (speedup 1.0000x reference)
#include <cuda_runtime.h>
#include <cuda_fp16.h>
#include <cstdint>

#define B_ 2
#define L_ 2048
#define E_ 1024
#define H_ 16
#define D_ 64
#define BL_ (B_*L_)
#define BH_ (B_*H_)

// ---------------- scratch (device globals) ---------------------------------
__device__ __half g_Qp[(size_t)BH_ * L_ * 128];
__device__ __half g_Kt[(size_t)BH_ * L_ * 64];   // raw kt  (t-proj)
__device__ __half g_Ks[(size_t)BH_ * L_ * 64];   // raw ks  (s-proj)
__device__ __half g_Vp[(size_t)BH_ * L_ * 64];
__device__ __half g_y [(size_t)BL_ * E_];
__device__ __half g_xth[(size_t)BL_ * E_];
__device__ __half g_xsh[(size_t)BL_ * E_];
__device__ __half g_WtT[(size_t)E_ * 3*E_];
__device__ __half g_WsT[(size_t)E_ * 2*E_];
__device__ __half g_WcT[(size_t)E_ * E_];

// Q scale: 1/sqrt(64) * log2(e)  (softmax runs in base-2 domain)
#define QS 0.18033688011112042f

// ---------------- helpers ----------------------------------------------------
union H2U { __half2 h; uint32_t u; };
__device__ __forceinline__ uint32_t h2u(__half2 v){ H2U x; x.h = v; return x.u; }
__device__ __forceinline__ __half2 u2h(uint32_t v){ H2U x; x.u = v; return x.h; }

__device__ __forceinline__ float ex2f(float x){
    float r; asm("ex2.approx.f32 %0, %1;" : "=f"(r) : "f"(x)); return r;
}
__device__ __forceinline__ uint32_t h2ex2(uint32_t x){
    uint32_t r; asm("ex2.approx.f16x2 %0, %1;" : "=r"(r) : "r"(x)); return r;
}
__device__ __forceinline__ void mma_f16(float c[4],
    uint32_t a0,uint32_t a1,uint32_t a2,uint32_t a3,uint32_t b0,uint32_t b1){
    asm volatile("mma.sync.aligned.m16n8k16.row.col.f32.f16.f16.f32 "
        "{%0,%1,%2,%3}, {%4,%5,%6,%7}, {%8,%9}, {%0,%1,%2,%3};"
        : "+f"(c[0]),"+f"(c[1]),"+f"(c[2]),"+f"(c[3])
        : "r"(a0),"r"(a1),"r"(a2),"r"(a3),"r"(b0),"r"(b1));
}
__device__ __forceinline__ void ldsm4(uint32_t& r0,uint32_t& r1,uint32_t& r2,uint32_t& r3,
                                      uint32_t addr){
    asm volatile("ldmatrix.sync.aligned.m8n8.x4.shared.b16 {%0,%1,%2,%3}, [%4];"
        : "=r"(r0),"=r"(r1),"=r"(r2),"=r"(r3) : "r"(addr));
}
__device__ __forceinline__ void ldsm4t(uint32_t& r0,uint32_t& r1,uint32_t& r2,uint32_t& r3,
                                       uint32_t addr){
    asm volatile("ldmatrix.sync.aligned.m8n8.x4.trans.shared.b16 {%0,%1,%2,%3}, [%4];"
        : "=r"(r0),"=r"(r1),"=r"(r2),"=r"(r3) : "r"(addr));
}
__device__ __forceinline__ void cp16(uint32_t dst, const void* src){
    asm volatile("cp.async.cg.shared.global [%0], [%1], 16;" :: "r"(dst), "l"(src));
}
__device__ __forceinline__ void cp_commit(){ asm volatile("cp.async.commit_group;"); }
template<int N> __device__ __forceinline__ void cp_wait(){
    asm volatile("cp.async.wait_group %0;" :: "n"(N));
}
__device__ __forceinline__ uint32_t s2u(const void* p){
    return (uint32_t)__cvta_generic_to_shared(p);
}

// ---------------- fp32 -> fp16 conversion (32 elems/thread, MLP=8) ----------
__global__ __launch_bounds__(256) void cvt_h_kernel(
    const float* __restrict__ in, __half* __restrict__ out, int n32)
{
    int i = blockIdx.x*blockDim.x + threadIdx.x;
    if (i < n32){
        const float4* p = (const float4*)(in + (size_t)i*32);
        float4 f[8];
#pragma unroll
        for (int j=0;j<8;j++) f[j] = p[j];
        __half2 h[16];
#pragma unroll
        for (int j=0;j<8;j++){
            h[2*j  ] = __floats2half2_rn(f[j].x, f[j].y);
            h[2*j+1] = __floats2half2_rn(f[j].z, f[j].w);
        }
        float4* q = (float4*)(out + (size_t)i*32);
#pragma unroll
        for (int j=0;j<4;j++) q[j] = *(float4*)&h[4*j];
    }
}

// ---------------- GEMM core: fp16 mma, 3-stage, 1 sync/iter ------------------
// BM=128, BN=128, BK=32(half), 8 warps (2x4), warp tile 64x32.
// MODE 0: fp32 C + bias. MODE 1: t-proj -> Qp-left/Kt/Vp. MODE 2: s-proj -> Qp-right/Ks.
#define ASTR 40
#define BSTR 136
#define GH_STAGE (128*ASTR + 32*BSTR)     // halfs per stage
template<int MODE>
__global__ __launch_bounds__(256, 2) void gemm_h(
    const __half* __restrict__ A, const __half* __restrict__ W,
    const float* __restrict__ bias, float* __restrict__ C,
    int N, int K)
{
    extern __shared__ __half smh[];
    const int tid = threadIdx.x, lane = tid & 31, warp = tid >> 5;
    const int wm = warp >> 2, wn = warp & 3, gid = lane >> 2, tig = lane & 3;
    const int bM = blockIdx.y * 128, bN = blockIdx.x * 128;
    const uint32_t sbase = s2u(smh);

    float c[4][4][4];
#pragma unroll
    for (int i=0;i<4;i++)
#pragma unroll
        for (int j=0;j<4;j++)
#pragma unroll
            for (int r=0;r<4;r++) c[i][j][r]=0.f;

    const int niter = K >> 5;
    const int lrow = (lane & 7) + ((lane >> 3) & 1) * 8;
    const int lcol = (lane >> 4) * 8;

    auto load_chunk = [&](int ch_k, int s){
        const uint32_t aBuf = sbase + (uint32_t)(s*GH_STAGE)*2;
        const uint32_t bBuf = aBuf + (uint32_t)(128*ASTR)*2;
        const int k0 = ch_k * 32;
#pragma unroll
        for (int i=0;i<2;i++){
            int ch = tid + i*256, row = ch>>2, colh = (ch&3)*8;
            cp16(aBuf + (uint32_t)(row*ASTR + colh)*2,
                 A + (size_t)(bM+row)*K + k0 + colh);
        }
#pragma unroll
        for (int i=0;i<2;i++){
            int ch = tid + i*256, row = ch>>4, colh = (ch&15)*8;
            cp16(bBuf + (uint32_t)(row*BSTR + colh)*2,
                 W + (size_t)(k0+row)*N + bN + colh);
        }
        cp_commit();
    };

    load_chunk(0, 0);
    load_chunk(1, 1);

    for (int it = 0; it < niter; it++){
        if (it < niter-1) cp_wait<1>(); else cp_wait<0>();
        __syncthreads();
        if (it + 2 < niter) load_chunk(it+2, (it+2)%3);

        const int s = it % 3;
        const uint32_t aBase = sbase + (uint32_t)(s*GH_STAGE)*2;
        const uint32_t bBase = aBase + (uint32_t)(128*ASTR)*2;
#pragma unroll
        for (int kk = 0; kk < 2; kk++){
            const int kb = kk*16;
            uint32_t a[4][4], b[4][2];
#pragma unroll
            for (int i=0;i<4;i++){
                const int r = wm*64 + i*16 + lrow;
                ldsm4(a[i][0],a[i][1],a[i][2],a[i][3],
                      aBase + (uint32_t)(r*ASTR + kb + lcol)*2);
            }
#pragma unroll
            for (int jj=0;jj<2;jj++){
                const int krow = kb + lrow;
                const int nc = wn*32 + jj*16 + lcol;
                uint32_t r0,r1,r2,r3;
                ldsm4t(r0,r1,r2,r3, bBase + (uint32_t)(krow*BSTR + nc)*2);
                b[jj*2  ][0]=r0; b[jj*2  ][1]=r1;
                b[jj*2+1][0]=r2; b[jj*2+1][1]=r3;
            }
#pragma unroll
            for (int i=0;i<4;i++)
#pragma unroll
                for (int j=0;j<4;j++)
                    mma_f16(c[i][j], a[i][0],a[i][1],a[i][2],a[i][3], b[j][0],b[j][1]);
        }
    }

    // -------- epilogue --------
#pragma unroll
    for (int i=0;i<4;i++){
        const int row0 = bM + wm*64 + i*16 + gid;
#pragma unroll
        for (int j=0;j<4;j++){
            const int col = bN + wn*32 + j*8 + tig*2;
            const float b0 = bias[col], b1 = bias[col+1];
#pragma unroll
            for (int half_ = 0; half_ < 2; half_++){
                const int r = row0 + half_*8;
                const float v0 = c[i][j][half_*2  ] + b0;
                const float v1 = c[i][j][half_*2+1] + b1;
                if (MODE == 0){
                    *(float2*)(C + (size_t)r*N + col) = make_float2(v0, v1);
                } else {
                    const int bb = r >> 11, l = r & 2047;
                    if (MODE == 1){
                        if (col < 1024){
                            const int h = col>>6, d = col&63;
                            const size_t o = ((size_t)((bb<<4)+h)*L_ + l)*128 + d;
                            *(__half2*)&g_Qp[o] = __floats2half2_rn(v0*QS, v1*QS);
                        } else if (col < 2048){
                            const int cc = col-1024, h = cc>>6, d = cc&63;
                            const size_t o = ((size_t)((bb<<4)+h)*L_ + l)*64 + d;
                            *(__half2*)&g_Kt[o] = __floats2half2_rn(v0, v1);
                        } else {
                            const int cc = col-2048, h = cc>>6, d = cc&63;
                            const size_t o = ((size_t)((bb<<4)+h)*L_ + l)*64 + d;
                            *(__half2*)&g_Vp[o] = __floats2half2_rn(v0, v1);
                        }
                    } else { // MODE 2
                        if (col < 1024){
                            const int h = col>>6, d = col&63;
                            const size_t o = ((size_t)((bb<<4)+h)*L_ + l)*128 + 64 + d;
                            *(__half2*)&g_Qp[o] = __floats2half2_rn(v0*QS, v1*QS);
                        } else {
                            const int cc = col-1024, h = cc>>6, d = cc&63;
                            const size_t o = ((size_t)((bb<<4)+h)*L_ + l)*64 + d;
                            *(__half2*)&g_Ks[o] = __floats2half2_rn(v0, v1);
                        }
                    }
                }
            }
        }
    }
}

// ---------------- flash attention: BQ=128, BK=64 ----------------------------
// raw kt/ks/v via 2-stage cp.async; fp32 in-kernel lambda combine -> Kc.
#define RAWS 4608                 // 64*72
#define OFF_KS (2*RAWS)
#define OFF_V  (4*RAWS)
#define OFF_KC (6*RAWS)
#define KSTR 136
#define VSTR 72
#define ATTN_HALFS (OFF_KC + 64*KSTR)   // 36352 halfs = 72704 B
#define NT 32
__global__ __launch_bounds__(256, 2) void attn_h(
    const float* __restrict__ lam_ts, const float* __restrict__ lam_st,
    const float* __restrict__ lam_ss)
{
    extern __shared__ __half smh[];
    const int tid = threadIdx.x, lane = tid & 31, warp = tid >> 5;
    const int gid = lane >> 2, tig = lane & 3;
    const int bh = blockIdx.y, q0 = blockIdx.x * 128;
    const int w16 = warp * 16;
    const int lrow = (lane & 7) + ((lane >> 3) & 1) * 8;
    const int lcol = (lane >> 4) * 8;

    const float vts = lam_ts[0], vst = lam_st[0], vss = lam_ss[0];

    const __half* Qg  = g_Qp + (size_t)bh * L_ * 128;
    const __half* Ktg = g_Kt + (size_t)bh * L_ * 64;
    const __half* Ksg = g_Ks + (size_t)bh * L_ * 64;
    const __half* Vg  = g_Vp + (size_t)bh * L_ * 64;
    const uint32_t sbase = s2u(smh);
    const uint32_t kcBase = sbase + (uint32_t)OFF_KC*2;

    uint32_t qa[8][4];
    {
        const __half* q0p = Qg + (size_t)(q0 + w16 + gid)*128;
        const __half* q1p = q0p + 8*128;
#pragma unroll
        for (int kk=0;kk<8;kk++){
            qa[kk][0] = *(const uint32_t*)(q0p + kk*16 + 2*tig);
            qa[kk][1] = *(const uint32_t*)(q1p + kk*16 + 2*tig);
            qa[kk][2] = *(const uint32_t*)(q0p + kk*16 + 8 + 2*tig);
            qa[kk][3] = *(const uint32_t*)(q1p + kk*16 + 8 + 2*tig);
        }
    }

    auto load_raw = [&](int t, int s){
        const uint32_t ktB = sbase + (uint32_t)(s*RAWS)*2;
        const uint32_t ksB = sbase + (uint32_t)(OFF_KS + s*RAWS)*2;
        const uint32_t vB  = sbase + (uint32_t)(OFF_V  + s*RAWS)*2;
        const int r0g = t*64;
#pragma unroll
        for (int i=0;i<2;i++){
            int ch = tid + i*256, row = ch>>3, c8 = (ch&7)*8;
            const size_t go = (size_t)(r0g+row)*64 + c8;
            const uint32_t so = (uint32_t)(row*72 + c8)*2;
            cp16(ktB + so, Ktg + go);
            cp16(ksB + so, Ksg + go);
            cp16(vB  + so, Vg  + go);
        }
        cp_commit();
    };

    float o[8][4];
#pragma unroll
    for (int j=0;j<8;j++){ o[j][0]=0.f; o[j][1]=0.f; o[j][2]=0.f; o[j][3]=0.f; }
    float mA = -1e30f, mB = -1e30f, lA = 0.f, lB = 0.f;

    load_raw(0, 0);

    for (int t = 0; t < NT; t++){
        cp_wait<0>();
        __syncthreads();
        if (t + 1 < NT) load_raw(t+1, (t+1)&1);

        // ---- fp32 lambda-combine: raw kt/ks -> Kc [64][136] (k1 | k2) -------
        {
            const int s = t & 1;
            const int key = tid >> 2, q = tid & 3;
            const __half2* ktp = (const __half2*)(smh + s*RAWS + key*72 + q*16);
            const __half2* ksp = (const __half2*)(smh + OFF_KS + s*RAWS + key*72 + q*16);
            __half2 k1h[8], k2h[8];
#pragma unroll
            for (int i=0;i<8;i++){
                float2 a = __half22float2(ktp[i]);
                float2 b = __half22float2(ksp[i]);
                k1h[i] = __floats2half2_rn(a.x + vts*b.x, a.y + vts*b.y);
                k2h[i] = __floats2half2_rn(vst*a.x + vss*b.x, vst*a.y + vss*b.y);
            }
            __half* kc = smh + OFF_KC + key*136 + q*16;
            *(uint4*)(kc)          = *(uint4*)&k1h[0];
            *(uint4*)(kc + 8)      = *(uint4*)&k1h[4];
            *(uint4*)(kc + 64)     = *(uint4*)&k2h[0];
            *(uint4*)(kc + 64 + 8) = *(uint4*)&k2h[4];
        }
        __syncthreads();

        const uint32_t vBase = sbase + (uint32_t)(OFF_V + (t&1)*RAWS)*2;

        // S = Q @ K^T
        float sc[8][4];
#pragma unroll
        for (int j=0;j<8;j++){ sc[j][0]=0.f; sc[j][1]=0.f; sc[j][2]=0.f; sc[j][3]=0.f; }
        const int krow = (lane & 7) + (lane >> 4) * 8;
        const int kcol = ((lane >> 3) & 1) * 8;
#pragma unroll
        for (int kk=0;kk<8;kk++){
            const int kb = kk*16;
#pragma unroll
            for (int jj=0;jj<4;jj++){
                uint32_t b0,b1,b2,b3;
                ldsm4(b0,b1,b2,b3,
                    kcBase + (uint32_t)((jj*16 + krow)*KSTR + kb + kcol)*2);
                mma_f16(sc[jj*2  ], qa[kk][0],qa[kk][1],qa[kk][2],qa[kk][3], b0,b1);
                mma_f16(sc[jj*2+1], qa[kk][0],qa[kk][1],qa[kk][2],qa[kk][3], b2,b3);
            }
        }

        // online softmax (base-2 domain)
        float rmA = -1e30f, rmB = -1e30f;
#pragma unroll
        for (int j=0;j<8;j++){
            rmA = fmaxf(rmA, fmaxf(sc[j][0], sc[j][1]));
            rmB = fmaxf(rmB, fmaxf(sc[j][2], sc[j][3]));
        }
        rmA = fmaxf(rmA, __shfl_xor_sync(0xffffffffu, rmA, 1));
        rmA = fmaxf(rmA, __shfl_xor_sync(0xffffffffu, rmA, 2));
        rmB = fmaxf(rmB, __shfl_xor_sync(0xffffffffu, rmB, 1));
        rmB = fmaxf(rmB, __shfl_xor_sync(0xffffffffu, rmB, 2));
        const float nmA = fmaxf(mA, rmA), nmB = fmaxf(mB, rmB);
        const float aA = ex2f(mA - nmA), aB = ex2f(mB - nmB);
        mA = nmA; mB = nmB;

        uint32_t pa[4][4];
        float sumA = 0.f, sumB = 0.f;
#pragma unroll
        for (int kk=0;kk<4;kk++){
            uint32_t e0 = h2ex2(h2u(__floats2half2_rn(sc[2*kk  ][0]-nmA, sc[2*kk  ][1]-nmA)));
            uint32_t e1 = h2ex2(h2u(__floats2half2_rn(sc[2*kk  ][2]-nmB, sc[2*kk  ][3]-nmB)));
            uint32_t e2 = h2ex2(h2u(__floats2half2_rn(sc[2*kk+1][0]-nmA, sc[2*kk+1][1]-nmA)));
            uint32_t e3 = h2ex2(h2u(__floats2half2_rn(sc[2*kk+1][2]-nmB, sc[2*kk+1][3]-nmB)));
            pa[kk][0]=e0; pa[kk][1]=e1; pa[kk][2]=e2; pa[kk][3]=e3;
            float2 f;
            f = __half22float2(u2h(e0)); sumA += f.x + f.y;
            f = __half22float2(u2h(e2)); sumA += f.x + f.y;
            f = __half22float2(u2h(e1)); sumB += f.x + f.y;
            f = __half22float2(u2h(e3)); sumB += f.x + f.y;
        }
#pragma unroll
        for (int j=0;j<8;j++){
            o[j][0]*=aA; o[j][1]*=aA; o[j][2]*=aB; o[j][3]*=aB;
        }
        sumA += __shfl_xor_sync(0xffffffffu, sumA, 1);
        sumA += __shfl_xor_sync(0xffffffffu, sumA, 2);
        sumB += __shfl_xor_sync(0xffffffffu, sumB, 1);
        sumB += __shfl_xor_sync(0xffffffffu, sumB, 2);
        lA = lA*aA + sumA; lB = lB*aB + sumB;

        // O += P @ V
#pragma unroll
        for (int kk=0;kk<4;kk++){
            const int kb = kk*16;
#pragma unroll
            for (int jj=0;jj<4;jj++){
                uint32_t b0,b1,b2,b3;
                ldsm4t(b0,b1,b2,b3,
                    vBase + (uint32_t)((kb + lrow)*VSTR + jj*16 + lcol)*2);
                mma_f16(o[jj*2  ], pa[kk][0],pa[kk][1],pa[kk][2],pa[kk][3], b0,b1);
                mma_f16(o[jj*2+1], pa[kk][0],pa[kk][1],pa[kk][2],pa[kk][3], b2,b3);
            }
        }
    }

    const int b = bh / H_, h = bh % H_;
    const float iA = 1.f/lA, iB = 1.f/lB;
    const int rowA = b*L_ + q0 + w16 + gid;
#pragma unroll
    for (int j=0;j<8;j++){
        const int col = h*64 + j*8 + tig*2;
        __half2 vA = __floats2half2_rn(o[j][0]*iA, o[j][1]*iA);
        __half2 vB = __floats2half2_rn(o[j][2]*iB, o[j][3]*iB);
        *(__half2*)&g_y[(size_t)rowA    *E_ + col] = vA;
        *(__half2*)&g_y[(size_t)(rowA+8)*E_ + col] = vB;
    }
}

// ---------------- launch ----------------------------------------------------
extern "C" void kernel_launch(void* const* d_in, const int* in_sizes, int n_in,
                              void* d_out, int out_size)
{
    const float* xt  = (const float*)d_in[0];
    const float* xs  = (const float*)d_in[1];
    const float* Wt  = (const float*)d_in[2];
    const float* bt  = (const float*)d_in[3];
    const float* Ws  = (const float*)d_in[4];
    const float* bs  = (const float*)d_in[5];
    const float* Wc  = (const float*)d_in[6];
    const float* bc  = (const float*)d_in[7];
    const float* lts = (const float*)d_in[8];
    const float* lst = (const float*)d_in[9];
    const float* lss = (const float*)d_in[10];
    float* out = (float*)d_out;

    __half *y, *xth, *xsh, *WtT, *WsT, *WcT;
    cudaGetSymbolAddress((void**)&y,    g_y);
    cudaGetSymbolAddress((void**)&xth,  g_xth);
    cudaGetSymbolAddress((void**)&xsh,  g_xsh);
    cudaGetSymbolAddress((void**)&WtT,  g_WtT);
    cudaGetSymbolAddress((void**)&WsT,  g_WsT);
    cudaGetSymbolAddress((void**)&WcT,  g_WcT);

    const int GEMM_SMEM = 3 * GH_STAGE * 2;    // 56832 B
    const int ATTN_SMEM = ATTN_HALFS * 2;      // 72704 B
    cudaFuncSetAttribute(gemm_h<0>,
        cudaFuncAttributeMaxDynamicSharedMemorySize, GEMM_SMEM);
    cudaFuncSetAttribute(gemm_h<1>,
        cudaFuncAttributeMaxDynamicSharedMemorySize, GEMM_SMEM);
    cudaFuncSetAttribute(gemm_h<2>,
        cudaFuncAttributeMaxDynamicSharedMemorySize, GEMM_SMEM);
    cudaFuncSetAttribute(attn_h,
        cudaFuncAttributeMaxDynamicSharedMemorySize, ATTN_SMEM);

    // ---- streams: s1 = s-path, s2 = Wt conversion (parallel to xt) ----------
    cudaStream_t s1, s2;
    cudaEvent_t eFork, eJoin, eWt;
    cudaStreamCreateWithFlags(&s1, cudaStreamNonBlocking);
    cudaStreamCreateWithFlags(&s2, cudaStreamNonBlocking);
    cudaEventCreateWithFlags(&eFork, cudaEventDisableTiming);
    cudaEventCreateWithFlags(&eJoin, cudaEventDisableTiming);
    cudaEventCreateWithFlags(&eWt,   cudaEventDisableTiming);

    cudaEventRecord(eFork, 0);
    cudaStreamWaitEvent(s1, eFork, 0);
    cudaStreamWaitEvent(s2, eFork, 0);

    // stream 0: xt cvt;  stream 2: Wt cvt (independent -> parallel)
    cvt_h_kernel<<<(BL_*E_/32 + 255)/256, 256>>>(xt, xth, BL_*E_/32);
    cvt_h_kernel<<<(E_*3*E_/32 + 255)/256, 256, 0, s2>>>(Wt, WtT, E_*3*E_/32);
    cudaEventRecord(eWt, s2);
    cudaStreamWaitEvent(0, eWt, 0);
    // t-proj: xt @ Wt + bt -> Qp-left / Kt / Vp
    gemm_h<1><<<dim3(3*E_/128, BL_/128), 256, GEMM_SMEM>>>(
        xth, WtT, bt, nullptr, 3*E_, E_);

    // stream 1: s-path (cvt xs/Ws/Wc, s-proj) — concurrent with t-path
    cvt_h_kernel<<<(BL_*E_/32 + 255)/256, 256, 0, s1>>>(xs, xsh, BL_*E_/32);
    cvt_h_kernel<<<(E_*2*E_/32 + 255)/256, 256, 0, s1>>>(Ws, WsT, E_*2*E_/32);
    cvt_h_kernel<<<(E_*E_/32 + 255)/256, 256, 0, s1>>>(Wc, WcT, E_*E_/32);
    gemm_h<2><<<dim3(2*E_/128, BL_/128), 256, GEMM_SMEM, s1>>>(
        xsh, WsT, bs, nullptr, 2*E_, E_);
    cudaEventRecord(eJoin, s1);

    // join, then attention + out-proj
    cudaStreamWaitEvent(0, eJoin, 0);
    attn_h<<<dim3(L_/128, BH_), 256, ATTN_SMEM>>>(lts, lst, lss);
    gemm_h<0><<<dim3(E_/128, BL_/128), 256, GEMM_SMEM>>>(
        y, WcT, bc, out, E_, E_);

    cudaEventDestroy(eFork);
    cudaEventDestroy(eJoin);
    cudaEventDestroy(eWt);
    cudaStreamDestroy(s1);
    cudaStreamDestroy(s2);
}

// round 15
// speedup vs baseline: 1.0106x; 1.0106x over previous
#include <cuda_runtime.h>
#include <cuda_fp16.h>
#include <cstdint>

#define B_ 2
#define L_ 2048
#define E_ 1024
#define H_ 16
#define D_ 64
#define BL_ (B_*L_)
#define BH_ (B_*H_)

// ---------------- scratch (device globals) ---------------------------------
__device__ __half g_Qp[(size_t)BH_ * L_ * 128];
__device__ __half g_Kt[(size_t)BH_ * L_ * 64];   // raw kt  (t-proj)
__device__ __half g_Ks[(size_t)BH_ * L_ * 64];   // raw ks  (s-proj)
__device__ __half g_Vp[(size_t)BH_ * L_ * 64];
__device__ __half g_y [(size_t)BL_ * E_];
__device__ __half g_xth[(size_t)BL_ * E_];
__device__ __half g_xsh[(size_t)BL_ * E_];
__device__ __half g_WtT[(size_t)E_ * 3*E_];
__device__ __half g_WsT[(size_t)E_ * 2*E_];
__device__ __half g_WcT[(size_t)E_ * E_];

// Q scale: 1/sqrt(64) * log2(e)  (softmax runs in base-2 domain)
#define QS 0.18033688011112042f

// ---------------- helpers ----------------------------------------------------
union H2U { __half2 h; uint32_t u; };
__device__ __forceinline__ uint32_t h2u(__half2 v){ H2U x; x.h = v; return x.u; }
__device__ __forceinline__ __half2 u2h(uint32_t v){ H2U x; x.u = v; return x.h; }

__device__ __forceinline__ float ex2f(float x){
    float r; asm("ex2.approx.f32 %0, %1;" : "=f"(r) : "f"(x)); return r;
}
__device__ __forceinline__ uint32_t h2ex2(uint32_t x){
    uint32_t r; asm("ex2.approx.f16x2 %0, %1;" : "=r"(r) : "r"(x)); return r;
}
__device__ __forceinline__ void mma_f16(float c[4],
    uint32_t a0,uint32_t a1,uint32_t a2,uint32_t a3,uint32_t b0,uint32_t b1){
    asm volatile("mma.sync.aligned.m16n8k16.row.col.f32.f16.f16.f32 "
        "{%0,%1,%2,%3}, {%4,%5,%6,%7}, {%8,%9}, {%0,%1,%2,%3};"
        : "+f"(c[0]),"+f"(c[1]),"+f"(c[2]),"+f"(c[3])
        : "r"(a0),"r"(a1),"r"(a2),"r"(a3),"r"(b0),"r"(b1));
}
__device__ __forceinline__ void ldsm4(uint32_t& r0,uint32_t& r1,uint32_t& r2,uint32_t& r3,
                                      uint32_t addr){
    asm volatile("ldmatrix.sync.aligned.m8n8.x4.shared.b16 {%0,%1,%2,%3}, [%4];"
        : "=r"(r0),"=r"(r1),"=r"(r2),"=r"(r3) : "r"(addr));
}
__device__ __forceinline__ void ldsm4t(uint32_t& r0,uint32_t& r1,uint32_t& r2,uint32_t& r3,
                                       uint32_t addr){
    asm volatile("ldmatrix.sync.aligned.m8n8.x4.trans.shared.b16 {%0,%1,%2,%3}, [%4];"
        : "=r"(r0),"=r"(r1),"=r"(r2),"=r"(r3) : "r"(addr));
}
__device__ __forceinline__ void cp16(uint32_t dst, const void* src){
    asm volatile("cp.async.cg.shared.global [%0], [%1], 16;" :: "r"(dst), "l"(src));
}
__device__ __forceinline__ void cp_commit(){ asm volatile("cp.async.commit_group;"); }
template<int N> __device__ __forceinline__ void cp_wait(){
    asm volatile("cp.async.wait_group %0;" :: "n"(N));
}
__device__ __forceinline__ uint32_t s2u(const void* p){
    return (uint32_t)__cvta_generic_to_shared(p);
}

// ---------------- fp32 -> fp16 conversion (8 elems/thread — measured best) ---
__global__ __launch_bounds__(256) void cvt_h_kernel(
    const float* __restrict__ in, __half* __restrict__ out, int n8)
{
    int i = blockIdx.x*blockDim.x + threadIdx.x;
    if (i < n8){
        float4 a = *(const float4*)(in + (size_t)i*8);
        float4 b = *(const float4*)(in + (size_t)i*8 + 4);
        __half2 h[4];
        h[0] = __floats2half2_rn(a.x, a.y);
        h[1] = __floats2half2_rn(a.z, a.w);
        h[2] = __floats2half2_rn(b.x, b.y);
        h[3] = __floats2half2_rn(b.z, b.w);
        *(float4*)(out + (size_t)i*8) = *(float4*)h;
    }
}

// ---------------- GEMM core: fp16 mma, 3-stage, 1 sync/iter ------------------
// BM=128, BN=128, BK=32(half), 8 warps (2x4), warp tile 64x32.
// MODE 0: fp32 C + bias. MODE 1: t-proj -> Qp-left/Kt/Vp. MODE 2: s-proj -> Qp-right/Ks.
#define ASTR 40
#define BSTR 136
#define GH_STAGE (128*ASTR + 32*BSTR)     // halfs per stage
template<int MODE>
__global__ __launch_bounds__(256, 2) void gemm_h(
    const __half* __restrict__ A, const __half* __restrict__ W,
    const float* __restrict__ bias, float* __restrict__ C,
    int N, int K)
{
    extern __shared__ __half smh[];
    const int tid = threadIdx.x, lane = tid & 31, warp = tid >> 5;
    const int wm = warp >> 2, wn = warp & 3, gid = lane >> 2, tig = lane & 3;
    const int bM = blockIdx.y * 128, bN = blockIdx.x * 128;
    const uint32_t sbase = s2u(smh);

    float c[4][4][4];
#pragma unroll
    for (int i=0;i<4;i++)
#pragma unroll
        for (int j=0;j<4;j++)
#pragma unroll
            for (int r=0;r<4;r++) c[i][j][r]=0.f;

    const int niter = K >> 5;
    const int lrow = (lane & 7) + ((lane >> 3) & 1) * 8;
    const int lcol = (lane >> 4) * 8;

    auto load_chunk = [&](int ch_k, int s){
        const uint32_t aBuf = sbase + (uint32_t)(s*GH_STAGE)*2;
        const uint32_t bBuf = aBuf + (uint32_t)(128*ASTR)*2;
        const int k0 = ch_k * 32;
#pragma unroll
        for (int i=0;i<2;i++){
            int ch = tid + i*256, row = ch>>2, colh = (ch&3)*8;
            cp16(aBuf + (uint32_t)(row*ASTR + colh)*2,
                 A + (size_t)(bM+row)*K + k0 + colh);
        }
#pragma unroll
        for (int i=0;i<2;i++){
            int ch = tid + i*256, row = ch>>4, colh = (ch&15)*8;
            cp16(bBuf + (uint32_t)(row*BSTR + colh)*2,
                 W + (size_t)(k0+row)*N + bN + colh);
        }
        cp_commit();
    };

    load_chunk(0, 0);
    load_chunk(1, 1);

    for (int it = 0; it < niter; it++){
        if (it < niter-1) cp_wait<1>(); else cp_wait<0>();
        __syncthreads();
        if (it + 2 < niter) load_chunk(it+2, (it+2)%3);

        const int s = it % 3;
        const uint32_t aBase = sbase + (uint32_t)(s*GH_STAGE)*2;
        const uint32_t bBase = aBase + (uint32_t)(128*ASTR)*2;
#pragma unroll
        for (int kk = 0; kk < 2; kk++){
            const int kb = kk*16;
            uint32_t a[4][4], b[4][2];
#pragma unroll
            for (int i=0;i<4;i++){
                const int r = wm*64 + i*16 + lrow;
                ldsm4(a[i][0],a[i][1],a[i][2],a[i][3],
                      aBase + (uint32_t)(r*ASTR + kb + lcol)*2);
            }
#pragma unroll
            for (int jj=0;jj<2;jj++){
                const int krow = kb + lrow;
                const int nc = wn*32 + jj*16 + lcol;
                uint32_t r0,r1,r2,r3;
                ldsm4t(r0,r1,r2,r3, bBase + (uint32_t)(krow*BSTR + nc)*2);
                b[jj*2  ][0]=r0; b[jj*2  ][1]=r1;
                b[jj*2+1][0]=r2; b[jj*2+1][1]=r3;
            }
#pragma unroll
            for (int i=0;i<4;i++)
#pragma unroll
                for (int j=0;j<4;j++)
                    mma_f16(c[i][j], a[i][0],a[i][1],a[i][2],a[i][3], b[j][0],b[j][1]);
        }
    }

    // -------- epilogue --------
#pragma unroll
    for (int i=0;i<4;i++){
        const int row0 = bM + wm*64 + i*16 + gid;
#pragma unroll
        for (int j=0;j<4;j++){
            const int col = bN + wn*32 + j*8 + tig*2;
            const float b0 = bias[col], b1 = bias[col+1];
#pragma unroll
            for (int half_ = 0; half_ < 2; half_++){
                const int r = row0 + half_*8;
                const float v0 = c[i][j][half_*2  ] + b0;
                const float v1 = c[i][j][half_*2+1] + b1;
                if (MODE == 0){
                    *(float2*)(C + (size_t)r*N + col) = make_float2(v0, v1);
                } else {
                    const int bb = r >> 11, l = r & 2047;
                    if (MODE == 1){
                        if (col < 1024){
                            const int h = col>>6, d = col&63;
                            const size_t o = ((size_t)((bb<<4)+h)*L_ + l)*128 + d;
                            *(__half2*)&g_Qp[o] = __floats2half2_rn(v0*QS, v1*QS);
                        } else if (col < 2048){
                            const int cc = col-1024, h = cc>>6, d = cc&63;
                            const size_t o = ((size_t)((bb<<4)+h)*L_ + l)*64 + d;
                            *(__half2*)&g_Kt[o] = __floats2half2_rn(v0, v1);
                        } else {
                            const int cc = col-2048, h = cc>>6, d = cc&63;
                            const size_t o = ((size_t)((bb<<4)+h)*L_ + l)*64 + d;
                            *(__half2*)&g_Vp[o] = __floats2half2_rn(v0, v1);
                        }
                    } else { // MODE 2
                        if (col < 1024){
                            const int h = col>>6, d = col&63;
                            const size_t o = ((size_t)((bb<<4)+h)*L_ + l)*128 + 64 + d;
                            *(__half2*)&g_Qp[o] = __floats2half2_rn(v0*QS, v1*QS);
                        } else {
                            const int cc = col-1024, h = cc>>6, d = cc&63;
                            const size_t o = ((size_t)((bb<<4)+h)*L_ + l)*64 + d;
                            *(__half2*)&g_Ks[o] = __floats2half2_rn(v0, v1);
                        }
                    }
                }
            }
        }
    }
}

// ---------------- flash attention: BQ=128, BK=64 ----------------------------
// raw kt/ks/v via 2-stage cp.async; fp32 in-kernel lambda combine -> Kc.
#define RAWS 4608                 // 64*72
#define OFF_KS (2*RAWS)
#define OFF_V  (4*RAWS)
#define OFF_KC (6*RAWS)
#define KSTR 136
#define VSTR 72
#define ATTN_HALFS (OFF_KC + 64*KSTR)   // 36352 halfs = 72704 B
#define NT 32
__global__ __launch_bounds__(256, 2) void attn_h(
    const float* __restrict__ lam_ts, const float* __restrict__ lam_st,
    const float* __restrict__ lam_ss)
{
    extern __shared__ __half smh[];
    const int tid = threadIdx.x, lane = tid & 31, warp = tid >> 5;
    const int gid = lane >> 2, tig = lane & 3;
    const int bh = blockIdx.y, q0 = blockIdx.x * 128;
    const int w16 = warp * 16;
    const int lrow = (lane & 7) + ((lane >> 3) & 1) * 8;
    const int lcol = (lane >> 4) * 8;

    const float vts = lam_ts[0], vst = lam_st[0], vss = lam_ss[0];

    const __half* Qg  = g_Qp + (size_t)bh * L_ * 128;
    const __half* Ktg = g_Kt + (size_t)bh * L_ * 64;
    const __half* Ksg = g_Ks + (size_t)bh * L_ * 64;
    const __half* Vg  = g_Vp + (size_t)bh * L_ * 64;
    const uint32_t sbase = s2u(smh);
    const uint32_t kcBase = sbase + (uint32_t)OFF_KC*2;

    uint32_t qa[8][4];
    {
        const __half* q0p = Qg + (size_t)(q0 + w16 + gid)*128;
        const __half* q1p = q0p + 8*128;
#pragma unroll
        for (int kk=0;kk<8;kk++){
            qa[kk][0] = *(const uint32_t*)(q0p + kk*16 + 2*tig);
            qa[kk][1] = *(const uint32_t*)(q1p + kk*16 + 2*tig);
            qa[kk][2] = *(const uint32_t*)(q0p + kk*16 + 8 + 2*tig);
            qa[kk][3] = *(const uint32_t*)(q1p + kk*16 + 8 + 2*tig);
        }
    }

    auto load_raw = [&](int t, int s){
        const uint32_t ktB = sbase + (uint32_t)(s*RAWS)*2;
        const uint32_t ksB = sbase + (uint32_t)(OFF_KS + s*RAWS)*2;
        const uint32_t vB  = sbase + (uint32_t)(OFF_V  + s*RAWS)*2;
        const int r0g = t*64;
#pragma unroll
        for (int i=0;i<2;i++){
            int ch = tid + i*256, row = ch>>3, c8 = (ch&7)*8;
            const size_t go = (size_t)(r0g+row)*64 + c8;
            const uint32_t so = (uint32_t)(row*72 + c8)*2;
            cp16(ktB + so, Ktg + go);
            cp16(ksB + so, Ksg + go);
            cp16(vB  + so, Vg  + go);
        }
        cp_commit();
    };

    float o[8][4];
#pragma unroll
    for (int j=0;j<8;j++){ o[j][0]=0.f; o[j][1]=0.f; o[j][2]=0.f; o[j][3]=0.f; }
    float mA = -1e30f, mB = -1e30f, lA = 0.f, lB = 0.f;

    load_raw(0, 0);

    for (int t = 0; t < NT; t++){
        cp_wait<0>();
        __syncthreads();
        if (t + 1 < NT) load_raw(t+1, (t+1)&1);

        // ---- fp32 lambda-combine: raw kt/ks -> Kc [64][136] (k1 | k2) -------
        {
            const int s = t & 1;
            const int key = tid >> 2, q = tid & 3;
            const __half2* ktp = (const __half2*)(smh + s*RAWS + key*72 + q*16);
            const __half2* ksp = (const __half2*)(smh + OFF_KS + s*RAWS + key*72 + q*16);
            __half2 k1h[8], k2h[8];
#pragma unroll
            for (int i=0;i<8;i++){
                float2 a = __half22float2(ktp[i]);
                float2 b = __half22float2(ksp[i]);
                k1h[i] = __floats2half2_rn(a.x + vts*b.x, a.y + vts*b.y);
                k2h[i] = __floats2half2_rn(vst*a.x + vss*b.x, vst*a.y + vss*b.y);
            }
            __half* kc = smh + OFF_KC + key*136 + q*16;
            *(uint4*)(kc)          = *(uint4*)&k1h[0];
            *(uint4*)(kc + 8)      = *(uint4*)&k1h[4];
            *(uint4*)(kc + 64)     = *(uint4*)&k2h[0];
            *(uint4*)(kc + 64 + 8) = *(uint4*)&k2h[4];
        }
        __syncthreads();

        const uint32_t vBase = sbase + (uint32_t)(OFF_V + (t&1)*RAWS)*2;

        // S = Q @ K^T
        float sc[8][4];
#pragma unroll
        for (int j=0;j<8;j++){ sc[j][0]=0.f; sc[j][1]=0.f; sc[j][2]=0.f; sc[j][3]=0.f; }
        const int krow = (lane & 7) + (lane >> 4) * 8;
        const int kcol = ((lane >> 3) & 1) * 8;
#pragma unroll
        for (int kk=0;kk<8;kk++){
            const int kb = kk*16;
#pragma unroll
            for (int jj=0;jj<4;jj++){
                uint32_t b0,b1,b2,b3;
                ldsm4(b0,b1,b2,b3,
                    kcBase + (uint32_t)((jj*16 + krow)*KSTR + kb + kcol)*2);
                mma_f16(sc[jj*2  ], qa[kk][0],qa[kk][1],qa[kk][2],qa[kk][3], b0,b1);
                mma_f16(sc[jj*2+1], qa[kk][0],qa[kk][1],qa[kk][2],qa[kk][3], b2,b3);
            }
        }

        // online softmax (base-2 domain)
        float rmA = -1e30f, rmB = -1e30f;
#pragma unroll
        for (int j=0;j<8;j++){
            rmA = fmaxf(rmA, fmaxf(sc[j][0], sc[j][1]));
            rmB = fmaxf(rmB, fmaxf(sc[j][2], sc[j][3]));
        }
        rmA = fmaxf(rmA, __shfl_xor_sync(0xffffffffu, rmA, 1));
        rmA = fmaxf(rmA, __shfl_xor_sync(0xffffffffu, rmA, 2));
        rmB = fmaxf(rmB, __shfl_xor_sync(0xffffffffu, rmB, 1));
        rmB = fmaxf(rmB, __shfl_xor_sync(0xffffffffu, rmB, 2));
        const float nmA = fmaxf(mA, rmA), nmB = fmaxf(mB, rmB);
        const float aA = ex2f(mA - nmA), aB = ex2f(mB - nmB);
        mA = nmA; mB = nmB;

        uint32_t pa[4][4];
        float sumA = 0.f, sumB = 0.f;
#pragma unroll
        for (int kk=0;kk<4;kk++){
            uint32_t e0 = h2ex2(h2u(__floats2half2_rn(sc[2*kk  ][0]-nmA, sc[2*kk  ][1]-nmA)));
            uint32_t e1 = h2ex2(h2u(__floats2half2_rn(sc[2*kk  ][2]-nmB, sc[2*kk  ][3]-nmB)));
            uint32_t e2 = h2ex2(h2u(__floats2half2_rn(sc[2*kk+1][0]-nmA, sc[2*kk+1][1]-nmA)));
            uint32_t e3 = h2ex2(h2u(__floats2half2_rn(sc[2*kk+1][2]-nmB, sc[2*kk+1][3]-nmB)));
            pa[kk][0]=e0; pa[kk][1]=e1; pa[kk][2]=e2; pa[kk][3]=e3;
            float2 f;
            f = __half22float2(u2h(e0)); sumA += f.x + f.y;
            f = __half22float2(u2h(e2)); sumA += f.x + f.y;
            f = __half22float2(u2h(e1)); sumB += f.x + f.y;
            f = __half22float2(u2h(e3)); sumB += f.x + f.y;
        }
#pragma unroll
        for (int j=0;j<8;j++){
            o[j][0]*=aA; o[j][1]*=aA; o[j][2]*=aB; o[j][3]*=aB;
        }
        sumA += __shfl_xor_sync(0xffffffffu, sumA, 1);
        sumA += __shfl_xor_sync(0xffffffffu, sumA, 2);
        sumB += __shfl_xor_sync(0xffffffffu, sumB, 1);
        sumB += __shfl_xor_sync(0xffffffffu, sumB, 2);
        lA = lA*aA + sumA; lB = lB*aB + sumB;

        // O += P @ V
#pragma unroll
        for (int kk=0;kk<4;kk++){
            const int kb = kk*16;
#pragma unroll
            for (int jj=0;jj<4;jj++){
                uint32_t b0,b1,b2,b3;
                ldsm4t(b0,b1,b2,b3,
                    vBase + (uint32_t)((kb + lrow)*VSTR + jj*16 + lcol)*2);
                mma_f16(o[jj*2  ], pa[kk][0],pa[kk][1],pa[kk][2],pa[kk][3], b0,b1);
                mma_f16(o[jj*2+1], pa[kk][0],pa[kk][1],pa[kk][2],pa[kk][3], b2,b3);
            }
        }
    }

    const int b = bh / H_, h = bh % H_;
    const float iA = 1.f/lA, iB = 1.f/lB;
    const int rowA = b*L_ + q0 + w16 + gid;
#pragma unroll
    for (int j=0;j<8;j++){
        const int col = h*64 + j*8 + tig*2;
        __half2 vA = __floats2half2_rn(o[j][0]*iA, o[j][1]*iA);
        __half2 vB = __floats2half2_rn(o[j][2]*iB, o[j][3]*iB);
        *(__half2*)&g_y[(size_t)rowA    *E_ + col] = vA;
        *(__half2*)&g_y[(size_t)(rowA+8)*E_ + col] = vB;
    }
}

// ---------------- launch ----------------------------------------------------
extern "C" void kernel_launch(void* const* d_in, const int* in_sizes, int n_in,
                              void* d_out, int out_size)
{
    const float* xt  = (const float*)d_in[0];
    const float* xs  = (const float*)d_in[1];
    const float* Wt  = (const float*)d_in[2];
    const float* bt  = (const float*)d_in[3];
    const float* Ws  = (const float*)d_in[4];
    const float* bs  = (const float*)d_in[5];
    const float* Wc  = (const float*)d_in[6];
    const float* bc  = (const float*)d_in[7];
    const float* lts = (const float*)d_in[8];
    const float* lst = (const float*)d_in[9];
    const float* lss = (const float*)d_in[10];
    float* out = (float*)d_out;

    __half *y, *xth, *xsh, *WtT, *WsT, *WcT;
    cudaGetSymbolAddress((void**)&y,    g_y);
    cudaGetSymbolAddress((void**)&xth,  g_xth);
    cudaGetSymbolAddress((void**)&xsh,  g_xsh);
    cudaGetSymbolAddress((void**)&WtT,  g_WtT);
    cudaGetSymbolAddress((void**)&WsT,  g_WsT);
    cudaGetSymbolAddress((void**)&WcT,  g_WcT);

    const int GEMM_SMEM = 3 * GH_STAGE * 2;    // 56832 B
    const int ATTN_SMEM = ATTN_HALFS * 2;      // 72704 B
    cudaFuncSetAttribute(gemm_h<0>,
        cudaFuncAttributeMaxDynamicSharedMemorySize, GEMM_SMEM);
    cudaFuncSetAttribute(gemm_h<1>,
        cudaFuncAttributeMaxDynamicSharedMemorySize, GEMM_SMEM);
    cudaFuncSetAttribute(gemm_h<2>,
        cudaFuncAttributeMaxDynamicSharedMemorySize, GEMM_SMEM);
    cudaFuncSetAttribute(attn_h,
        cudaFuncAttributeMaxDynamicSharedMemorySize, ATTN_SMEM);

    // ---- streams: s1 = s-path, s2 = Wt conversion (parallel to xt) ----------
    cudaStream_t s1, s2;
    cudaEvent_t eFork, eJoin, eWt;
    cudaStreamCreateWithFlags(&s1, cudaStreamNonBlocking);
    cudaStreamCreateWithFlags(&s2, cudaStreamNonBlocking);
    cudaEventCreateWithFlags(&eFork, cudaEventDisableTiming);
    cudaEventCreateWithFlags(&eJoin, cudaEventDisableTiming);
    cudaEventCreateWithFlags(&eWt,   cudaEventDisableTiming);

    cudaEventRecord(eFork, 0);
    cudaStreamWaitEvent(s1, eFork, 0);
    cudaStreamWaitEvent(s2, eFork, 0);

    // stream 0: xt cvt;  stream 2: Wt cvt (independent -> parallel)
    cvt_h_kernel<<<(BL_*E_/8 + 255)/256, 256>>>(xt, xth, BL_*E_/8);
    cvt_h_kernel<<<(E_*3*E_/8 + 255)/256, 256, 0, s2>>>(Wt, WtT, E_*3*E_/8);
    cudaEventRecord(eWt, s2);
    cudaStreamWaitEvent(0, eWt, 0);
    // t-proj: xt @ Wt + bt -> Qp-left / Kt / Vp
    gemm_h<1><<<dim3(3*E_/128, BL_/128), 256, GEMM_SMEM>>>(
        xth, WtT, bt, nullptr, 3*E_, E_);

    // stream 1: s-path (cvt xs/Ws/Wc, s-proj) — concurrent with t-path
    cvt_h_kernel<<<(BL_*E_/8 + 255)/256, 256, 0, s1>>>(xs, xsh, BL_*E_/8);
    cvt_h_kernel<<<(E_*2*E_/8 + 255)/256, 256, 0, s1>>>(Ws, WsT, E_*2*E_/8);
    cvt_h_kernel<<<(E_*E_/8 + 255)/256, 256, 0, s1>>>(Wc, WcT, E_*E_/8);
    gemm_h<2><<<dim3(2*E_/128, BL_/128), 256, GEMM_SMEM, s1>>>(
        xsh, WsT, bs, nullptr, 2*E_, E_);
    cudaEventRecord(eJoin, s1);

    // join, then attention + out-proj
    cudaStreamWaitEvent(0, eJoin, 0);
    attn_h<<<dim3(L_/128, BH_), 256, ATTN_SMEM>>>(lts, lst, lss);
    gemm_h<0><<<dim3(E_/128, BL_/128), 256, GEMM_SMEM>>>(
        y, WcT, bc, out, E_, E_);

    cudaEventDestroy(eFork);
    cudaEventDestroy(eJoin);
    cudaEventDestroy(eWt);
    cudaStreamDestroy(s1);
    cudaStreamDestroy(s2);
}